// round 14
// baseline (speedup 1.0000x reference)
#include <cuda_runtime.h>
#include <cuda_fp16.h>

typedef unsigned short u16;
typedef unsigned int   u32;
typedef unsigned long long u64;

#define NODES 62
#define BATCHG 2048
#define NN (NODES*BATCHG)          // 126976
#define HROW 384                   // x:0-128 | x1:128-192 | x2:192-256 | x3:256-320 | x4:320-384
#define LINW 512
#define LIN2 256
#define KSPLIT 4
#define EPB 496

// ---------------- static device scratch ----------------
__device__ u16 g_Hh[(size_t)NN*HROW];          // H hi fp16
__device__ u16 g_Hl[(size_t)NN*HROW];          // H lo fp16 (only cols 0..127 ever read)
__device__ u16 g_Wt[4][5*192*64];              // cheb weights fp16, [blk][n][64]
__device__ u16 g_Wh1t[(size_t)248*512*64];     // Wh1 fp16 transposed blocks
__device__ u16 g_LA[4*4096];                   // [hl][kb][64 m][64 k] fp16 split of [L|L2]
__device__ float g_G1p[(size_t)KSPLIT*BATCHG*LINW];
__device__ float g_G1[BATCHG*LINW];
__device__ float g_G2[BATCHG*LIN2];
__device__ float g_S2p[2][32][LIN2];           // per-CTA G2 column partial sums
__device__ float g_L[62*64];
__device__ float g_L2[62*64];
__device__ float g_deg[64];
__device__ float g_mean[LINW];
__device__ float g_rstd[LINW];

// ---------------- helpers ----------------
__device__ __forceinline__ u32 smem_u32(const void* p){
    u32 a;
    asm("{ .reg .u64 t; cvta.to.shared.u64 t, %1; cvt.u32.u64 %0, t; }" : "=r"(a) : "l"(p));
    return a;
}
__device__ __forceinline__ void ldsm4(u32& r0,u32& r1,u32& r2,u32& r3,u32 addr){
    asm volatile("ldmatrix.sync.aligned.m8n8.x4.shared.b16 {%0,%1,%2,%3}, [%4];"
        : "=r"(r0),"=r"(r1),"=r"(r2),"=r"(r3) : "r"(addr));
}
__device__ __forceinline__ void mma_f16(float* d, const u32* a, const u32* b){
    asm volatile("mma.sync.aligned.m16n8k16.row.col.f32.f16.f16.f32 "
        "{%0,%1,%2,%3}, {%4,%5,%6,%7}, {%8,%9}, {%0,%1,%2,%3};"
        : "+f"(d[0]),"+f"(d[1]),"+f"(d[2]),"+f"(d[3])
        : "r"(a[0]),"r"(a[1]),"r"(a[2]),"r"(a[3]), "r"(b[0]),"r"(b[1]));
}
__device__ __forceinline__ u32 swz(u32 bo){ return bo ^ ((bo >> 3) & 0x70); }
__device__ __forceinline__ void splith(float v, u16& h, u16& l){
    __half hh = __float2half(v);
    __half ll = __float2half(v - __half2float(hh));
    h = *reinterpret_cast<u16*>(&hh);
    l = *reinterpret_cast<u16*>(&ll);
}
__device__ __forceinline__ u16 h16(float v){
    __half hh = __float2half(v);
    return *reinterpret_cast<u16*>(&hh);
}
__device__ __forceinline__ void cpa16(u32 dst, const void* src){
    asm volatile("cp.async.cg.shared.global [%0], [%1], 16;" :: "r"(dst), "l"(src));
}
__device__ __forceinline__ void cpa16_ca(u32 dst, const void* src){
    asm volatile("cp.async.ca.shared.global [%0], [%1], 16;" :: "r"(dst), "l"(src));
}
__device__ __forceinline__ void cpa_commit(){ asm volatile("cp.async.commit_group;"); }
template<int N> __device__ __forceinline__ void cpa_wait(){
    asm volatile("cp.async.wait_group %0;" :: "n"(N));
}

// ---------------- merged prep kernel: graphprep | prepW | prepWh1t | init_H ----
#define PB_W    1
#define PB_WH1  337
#define PB_INIT 2321
#define PB_TOT  6289

__global__ void k_prep_all(const float* __restrict__ x,
                           const int* __restrict__ row, const int* __restrict__ col,
                           const float* __restrict__ W0, const float* __restrict__ W1,
                           const float* __restrict__ W2, const float* __restrict__ W3,
                           const float* __restrict__ Wh1)
{
    int b = blockIdx.x;
    int tid = threadIdx.x;   // 512

    if (b == 0){
        int t = tid;
        if (t < 64) g_deg[t] = 0.f;
        for (int i = t; i < 62*64; i += 512){ g_L[i] = 0.f; g_L2[i] = 0.f; }
        __syncthreads();
        if (t < EPB) atomicAdd(&g_deg[row[t]], 1.0f);
        __syncthreads();
        if (t < EPB){
            int r = row[t], c = col[t];
            float w = -rsqrtf(g_deg[r]) * rsqrtf(g_deg[c]);
            atomicAdd(&g_L[r*64 + c], w);
        }
        __syncthreads();
        for (int i = t; i < 62*64; i += 512){
            int r = i >> 6, j = i & 63;
            float s = 0.f;
            if (j < 62)
                for (int m = 0; m < 62; m++) s += g_L[r*64+m] * g_L[m*64+j];
            g_L2[i] = s;
        }
        __syncthreads();
        for (int i = t; i < 8192; i += 512){
            int kb = i >> 12, rem = i & 4095;
            int m = rem >> 6, k = rem & 63;
            float val = 0.f;
            if (m < 62 && k < 62) val = kb ? g_L2[m*64+k] : g_L[m*64+k];
            u16 h, l; splith(val, h, l);
            g_LA[kb*4096 + rem] = h;
            g_LA[8192 + kb*4096 + rem] = l;
        }
    } else if (b < PB_WH1){
        int t = (b - PB_W)*512 + tid;
        if (t >= 172032) return;
        int layer, base, dreal;
        if (t < 24576)       { layer=0; base=0;      dreal=128; }
        else if (t < 61440)  { layer=1; base=24576;  dreal=190; }
        else if (t < 110592) { layer=2; base=61440;  dreal=252; }
        else                 { layer=3; base=110592; dreal=314; }
        const float* W = (layer==0) ? W0 : (layer==1) ? W1 : (layer==2) ? W2 : W3;
        int idx = t - base;
        int n = idx % 192, k = idx / 192;
        int ch = n >> 6, j = n & 63;
        float val = 0.f;
        int rr = -1;
        if (k < 128) rr = k;
        else { int q = k - 128; int chunk = q >> 6, w = q & 63; if (w < 62) rr = 128 + chunk*62 + w; }
        if (rr >= 0 && rr < dreal && j < 62) {
            const float* Wp0 = W;
            const float* Wp1 = W + (size_t)dreal*62;
            const float* Wp2 = W + (size_t)2*dreal*62;
            if (ch == 0)      val = Wp0[rr*62+j] - Wp2[rr*62+j];
            else if (ch == 1) val = Wp1[rr*62+j];
            else              val = 2.f * Wp2[rr*62+j];
        }
        int blk = k >> 6, kk = k & 63;
        g_Wt[layer][(size_t)blk*12288 + n*64 + kk] = h16(val);
    } else if (b < PB_INIT){
        int idx = (b - PB_WH1)*512 + tid;
        int n = idx & 511;
        int q = idx >> 9;
        int blk = q >> 3, c8 = (q & 7) * 8;
        union { u16 u[8]; uint4 v; } H;
#pragma unroll
        for (int i = 0; i < 8; i++){
            int k = blk*64 + c8 + i;
            int node = k >> 8, cc = k & 255, ch = cc >> 6, w = cc & 63;
            float val = 0.f;
            if (w < 62) val = Wh1[((size_t)(node*248 + ch*62 + w))*LINW + n];
            H.u[i] = h16(val);
        }
        *(uint4*)(g_Wh1t + ((size_t)blk*512 + n)*64 + c8) = H.v;
    } else {
        size_t idx = (size_t)(b - PB_INIT)*512 + tid;
        size_t r = idx >> 4;
        int c8 = ((int)idx & 15) * 8;
        float4 a = *(const float4*)(x + r*128 + c8);
        float4 bb4 = *(const float4*)(x + r*128 + c8 + 4);
        float v[8] = {a.x,a.y,a.z,a.w,bb4.x,bb4.y,bb4.z,bb4.w};
        union { u16 u[8]; uint4 q; } H, L;
#pragma unroll
        for (int i = 0; i < 8; i++) splith(v[i], H.u[i], L.u[i]);
        *(uint4*)(g_Hh + r*HROW + c8) = H.q;
        *(uint4*)(g_Hl + r*HROW + c8) = L.q;
    }
}

// ---------------- mma.sync cheb GEMM + MMA combine epilogue ----------------
#define CH_A_HI 0
#define CH_A_LO 16384
#define CH_B    32768
#define CH_BUF  57344
#define CH_ST   0
#define CH_BT   32768
#define CH_AL   65536
#define CH_SMEM (2*CH_BUF)   // 114688

__global__ __launch_bounds__(256,2) void mm_cheb(int layer, int Kdim,
                                                 const float* __restrict__ bias, int cbase)
{
    extern __shared__ char smem[];
    const u32 sb = smem_u32(smem);
    const int t = threadIdx.x, wid = t >> 5, l = t & 31;
    const int wm = (wid & 1) * 64, wn = (wid >> 1) * 48;
    const int m0 = blockIdx.x * 124;
    const int nch = Kdim >> 6;
    const u16* Bw = g_Wt[layer];

    float acc[4][6][4];
#pragma unroll
    for (int a = 0; a < 4; a++)
#pragma unroll
        for (int b = 0; b < 6; b++)
#pragma unroll
            for (int c = 0; c < 4; c++) acc[a][b][c] = 0.f;

    auto stage = [&](int c){
        u32 bufb = sb + (c & 1) * CH_BUF;
        int k0 = c << 6;
        bool useLo = (c < 2);
        for (int i = t; i < 1024; i += 256){
            int r = i >> 3, cc = i & 7;
            int gr = m0 + r; if (gr > NN-1) gr = NN-1;
            size_t go = (size_t)gr*HROW + k0 + cc*8;
            u32 bo = swz((u32)(r*128 + cc*16));
            cpa16(bufb + CH_A_HI + bo, g_Hh + go);
            if (useLo) cpa16(bufb + CH_A_LO + bo, g_Hl + go);
        }
        const u16* pb = Bw + (size_t)c*12288;
        for (int i = t; i < 1536; i += 256){
            int r = i >> 3, cc = i & 7;
            u32 bo = swz((u32)(r*128 + cc*16));
            cpa16_ca(bufb + CH_B + bo, pb + r*64 + cc*8);
        }
        cpa_commit();
    };

    stage(0);
    for (int c = 0; c < nch; c++){
        if (c+1 < nch) { stage(c+1); cpa_wait<1>(); }
        else cpa_wait<0>();
        __syncthreads();
        u32 bufb = sb + (c & 1) * CH_BUF;
        bool useLo = (c < 2);
#pragma unroll
        for (int ks = 0; ks < 4; ks++){
            int arow = wm + (l & 7) + ((l >> 3) & 1) * 8;
            int acol = ks*32 + ((l >> 4) & 1) * 16;
            int brow = wn + (l & 7) + ((l >> 4) & 1) * 8;
            int bcol = ks*32 + ((l >> 3) & 1) * 16;
            u32 aa[4][4];
#pragma unroll
            for (int mi = 0; mi < 4; mi++){
                u32 bo = swz((u32)((arow + mi*16)*128 + acol));
                ldsm4(aa[mi][0],aa[mi][1],aa[mi][2],aa[mi][3], bufb + CH_A_HI + bo);
            }
#pragma unroll
            for (int bi = 0; bi < 3; bi++){
                u32 bw4[4];
                u32 bo = swz((u32)((brow + bi*16)*128 + bcol));
                ldsm4(bw4[0],bw4[1],bw4[2],bw4[3], bufb + CH_B + bo);
#pragma unroll
                for (int mi = 0; mi < 4; mi++){
                    mma_f16(acc[mi][2*bi],   aa[mi], &bw4[0]);
                    mma_f16(acc[mi][2*bi+1], aa[mi], &bw4[2]);
                }
            }
            if (useLo){
#pragma unroll
                for (int mi = 0; mi < 4; mi++){
                    u32 bo = swz((u32)((arow + mi*16)*128 + acol));
                    ldsm4(aa[mi][0],aa[mi][1],aa[mi][2],aa[mi][3], bufb + CH_A_LO + bo);
                }
#pragma unroll
                for (int bi = 0; bi < 3; bi++){
                    u32 bw4[4];
                    u32 bo = swz((u32)((brow + bi*16)*128 + bcol));
                    ldsm4(bw4[0],bw4[1],bw4[2],bw4[3], bufb + CH_B + bo);
#pragma unroll
                    for (int mi = 0; mi < 4; mi++){
                        mma_f16(acc[mi][2*bi],   aa[mi], &bw4[0]);
                        mma_f16(acc[mi][2*bi+1], aa[mi], &bw4[2]);
                    }
                }
            }
        }
        __syncthreads();
    }

    // ---- combine epilogue: out = P0 + [L|L2]@[P1;P2], via MMA ----
    {
        int i = t;
        int g = i >> 7, kb = (i >> 6) & 1, feat = i & 63;
        u32 bo = CH_BT + g*16384 + kb*8192 + swz((u32)(feat*128 + 124));
        *(u32*)(smem + bo) = 0u;
    }
    for (int i = t; i < 2048; i += 256){
        int blk = i >> 9, rem = i & 511;
        int r = rem >> 3, cc = rem & 7;
        u32 bo = swz((u32)(r*128 + cc*16));
        *(float4*)(smem + CH_AL + blk*8192 + bo) = *(const float4*)(g_LA + blk*4096 + r*64 + cc*8);
    }
    __syncthreads();
    {
        float* stg = (float*)(smem + CH_ST);
#pragma unroll
        for (int mi = 0; mi < 4; mi++)
#pragma unroll
            for (int ni = 0; ni < 6; ni++)
#pragma unroll
                for (int rp = 0; rp < 4; rp += 2){
                    int row = wm + mi*16 + (l>>2) + (rp ? 8 : 0);
                    int col = wn + ni*8 + (l&3)*2;
                    float v0 = acc[mi][ni][rp], v1 = acc[mi][ni][rp+1];
                    if (col < 64){
                        *(float2*)&stg[row*64 + col] = make_float2(v0, v1);
                    } else if (row < 124){
                        int g = (row >= 62) ? 1 : 0;
                        int node = row - g*62;
                        int kbB = (col >= 128) ? 1 : 0;
                        int feat = col - (kbB ? 128 : 64);
                        u32 b0 = CH_BT + g*16384 + kbB*8192 + swz((u32)(feat*128 + node*2));
                        u32 b1 = CH_BT + g*16384 + kbB*8192 + swz((u32)((feat+1)*128 + node*2));
                        *(u16*)(smem + b0) = h16(v0);
                        *(u16*)(smem + b1) = h16(v1);
                    }
                }
    }
    __syncthreads();
    {
        int g = wid >> 2, mt = wid & 3;
        float a2[8][4];
#pragma unroll
        for (int j = 0; j < 8; j++)
#pragma unroll
            for (int r = 0; r < 4; r++) a2[j][r] = 0.f;
#pragma unroll
        for (int kb = 0; kb < 2; kb++)
#pragma unroll
            for (int k16 = 0; k16 < 4; k16++){
                u32 Ah[4], Al4[4];
                u32 boA = swz((u32)((mt*16 + (l&7) + ((l>>3)&1)*8)*128 + k16*32 + ((l>>4)&1)*16));
                ldsm4(Ah[0],Ah[1],Ah[2],Ah[3],     sb + CH_AL + kb*8192 + boA);
                ldsm4(Al4[0],Al4[1],Al4[2],Al4[3], sb + CH_AL + 16384 + kb*8192 + boA);
#pragma unroll
                for (int np = 0; np < 4; np++){
                    u32 Bw4[4];
                    u32 boB = swz((u32)((np*16 + (l&7) + ((l>>4)&1)*8)*128 + k16*32 + ((l>>3)&1)*16));
                    ldsm4(Bw4[0],Bw4[1],Bw4[2],Bw4[3], sb + CH_BT + g*16384 + kb*8192 + boB);
                    mma_f16(a2[2*np],   Ah,  &Bw4[0]);
                    mma_f16(a2[2*np],   Al4, &Bw4[0]);
                    mma_f16(a2[2*np+1], Ah,  &Bw4[2]);
                    mma_f16(a2[2*np+1], Al4, &Bw4[2]);
                }
            }
        float* stg = (float*)(smem + CH_ST);
        size_t hrow0 = ((size_t)(blockIdx.x*2 + g)) * 62;
#pragma unroll
        for (int j = 0; j < 8; j++)
#pragma unroll
            for (int rp = 0; rp < 4; rp += 2){
                int node = mt*16 + (l>>2) + (rp ? 8 : 0);
                if (node >= 62) continue;
                int col = j*8 + (l&3)*2;
                float v0 = a2[j][rp]   + stg[(g*62+node)*64 + col];
                float v1 = a2[j][rp+1] + stg[(g*62+node)*64 + col+1];
                v0 = (col   < 62) ? fmaxf(v0 + bias[col],   0.f) : 0.f;
                v1 = (col+1 < 62) ? fmaxf(v1 + bias[col+1], 0.f) : 0.f;
                size_t off = (hrow0 + node)*HROW + cbase + col;
                *(u32*)(g_Hh + off) = (u32)h16(v0) | ((u32)h16(v1) << 16);
            }
    }
}

// ---------------- mma.sync feats GEMM: A-hi only, 128x128 tile, 2 CTAs/SM ------
#define FT_A    0
#define FT_B    16384
#define FT_BUF  32768
#define FT_SMEM (2*FT_BUF)   // 65536

__global__ __launch_bounds__(256,2) void mm_feats()
{
    extern __shared__ char smem[];
    const u32 sb = smem_u32(smem);
    const int t = threadIdx.x, wid = t >> 5, l = t & 31;
    const int wm = (wid & 1) * 64, wn = (wid >> 1) * 32;
    const int n0 = blockIdx.x * 128;
    const int m0 = blockIdx.y * 128;
    const int part = blockIdx.z;
    const int cbeg = part * 62;

    float acc[4][4][4];
#pragma unroll
    for (int a = 0; a < 4; a++)
#pragma unroll
        for (int b = 0; b < 4; b++)
#pragma unroll
            for (int c = 0; c < 4; c++) acc[a][b][c] = 0.f;

    auto stage = [&](int cl){
        u32 bufb = sb + (cl & 1) * FT_BUF;
        int c = cbeg + cl;
        int node = c >> 2, col0 = 128 + ((c & 3) << 6);
        for (int i = t; i < 512; i += 256){
            int r = i >> 2, cc = (i & 3) * 2;
            size_t go = ((size_t)(m0 + r)*62 + node)*HROW + col0 + cc*8;
            cpa16(bufb + FT_A + swz((u32)(r*128 + cc*16)), g_Hh + go);
            cpa16(bufb + FT_A + swz((u32)(r*128 + (cc+1)*16)), g_Hh + go + 8);
        }
        const u16* pb = g_Wh1t + ((size_t)c*512 + n0)*64;
        for (int i = t; i < 1024; i += 256){
            int r = i >> 3, cc = i & 7;
            cpa16_ca(bufb + FT_B + swz((u32)(r*128 + cc*16)), pb + r*64 + cc*8);
        }
        cpa_commit();
    };

    stage(0);
    for (int cl = 0; cl < 62; cl++){
        if (cl+1 < 62) { stage(cl+1); cpa_wait<1>(); }
        else cpa_wait<0>();
        __syncthreads();
        u32 bufb = sb + (cl & 1) * FT_BUF;
#pragma unroll
        for (int ks = 0; ks < 4; ks++){
            u32 ah[4][4];
            int arow = wm + (l & 7) + ((l >> 3) & 1) * 8;
            int acol = ks*32 + ((l >> 4) & 1) * 16;
#pragma unroll
            for (int mi = 0; mi < 4; mi++){
                u32 bo = swz((u32)((arow + mi*16)*128 + acol));
                ldsm4(ah[mi][0],ah[mi][1],ah[mi][2],ah[mi][3], bufb + FT_A + bo);
            }
            u32 bw[2][4];
            int brow = wn + (l & 7) + ((l >> 4) & 1) * 8;
            int bcol = ks*32 + ((l >> 3) & 1) * 16;
#pragma unroll
            for (int bi = 0; bi < 2; bi++){
                u32 bo = swz((u32)((brow + bi*16)*128 + bcol));
                ldsm4(bw[bi][0],bw[bi][1],bw[bi][2],bw[bi][3], bufb + FT_B + bo);
            }
#pragma unroll
            for (int mi = 0; mi < 4; mi++)
#pragma unroll
                for (int bi = 0; bi < 2; bi++){
                    mma_f16(acc[mi][2*bi],   ah[mi], &bw[bi][0]);
                    mma_f16(acc[mi][2*bi+1], ah[mi], &bw[bi][2]);
                }
        }
        __syncthreads();
    }

    float* outp = g_G1p + (size_t)part*BATCHG*LINW;
#pragma unroll
    for (int mi = 0; mi < 4; mi++)
#pragma unroll
        for (int ni = 0; ni < 4; ni++){
            int row = m0 + wm + mi*16 + (l >> 2);
            int col = n0 + wn + ni*8 + (l & 3)*2;
            *(float2*)&outp[(size_t)row*LINW + col]     = make_float2(acc[mi][ni][0], acc[mi][ni][1]);
            *(float2*)&outp[(size_t)(row+8)*LINW + col] = make_float2(acc[mi][ni][2], acc[mi][ni][3]);
        }
}

// ---------------- fused split-K reduce + BN1 stats ----------------
__global__ void k_redstats(){
    int c0 = blockIdx.x * 8;
    int t = threadIdx.x;
    int c = c0 + (t & 7);
    float s = 0.f, sq = 0.f;
    for (int r = (t >> 3); r < BATCHG; r += 32){
        size_t off = (size_t)r*LINW + c;
        float v = g_G1p[off]
                + g_G1p[(size_t)BATCHG*LINW + off]
                + g_G1p[(size_t)2*BATCHG*LINW + off]
                + g_G1p[(size_t)3*BATCHG*LINW + off];
        g_G1[off] = v;
        s += v; sq += v*v;
    }
    __shared__ float sh[256], sh2[256];
    sh[t] = s; sh2[t] = sq; __syncthreads();
    for (int o = 128; o >= 8; o >>= 1){
        if (t < o){ sh[t] += sh[t+o]; sh2[t] += sh2[t+o]; }
        __syncthreads();
    }
    if (t < 8){
        float m = sh[t] * (1.f/BATCHG);
        float v = sh2[t] * (1.f/BATCHG) - m*m;
        g_mean[c0+t] = m;
        g_rstd[c0+t] = rsqrtf(v + 1e-5f);
    }
}

// ---------------- SIMT fp32 GEMM for Wh2, BN1+ReLU fused, G2 partial stats ----
__global__ void gemm_s_bn(const float* __restrict__ A, const float* __restrict__ B,
                          float* __restrict__ C,
                          const float* __restrict__ gamma, const float* __restrict__ beta)
{
    __shared__ float As[16][68];
    __shared__ float Bs[16][64];
    __shared__ float Ssum[16][64], Ssq[16][64];
    int t = threadIdx.x;
    int m0 = blockIdx.y * 64, n0 = blockIdx.x * 64;
    int ty = t >> 4, tx = t & 15;
    int am = t >> 2, ak = (t & 3) * 4;
    int bk = t >> 4, bn = (t & 15) * 4;
    float acc[4][4];
#pragma unroll
    for (int i = 0; i < 4; i++)
#pragma unroll
        for (int j = 0; j < 4; j++) acc[i][j] = 0.f;
    for (int k0 = 0; k0 < LINW; k0 += 16) {
        float4 av = *reinterpret_cast<const float4*>(A + (size_t)(m0+am)*LINW + k0 + ak);
        float va[4] = {av.x, av.y, av.z, av.w};
#pragma unroll
        for (int q = 0; q < 4; q++){
            int k = k0 + ak + q;
            va[q] = fmaxf((va[q] - g_mean[k]) * g_rstd[k] * gamma[k] + beta[k], 0.f);
            As[ak+q][am] = va[q];
        }
        float4 bv = *reinterpret_cast<const float4*>(B + (size_t)(k0+bk)*LIN2 + n0 + bn);
        *reinterpret_cast<float4*>(&Bs[bk][bn]) = bv;
        __syncthreads();
#pragma unroll
        for (int k = 0; k < 16; k++) {
            float4 a4 = *reinterpret_cast<const float4*>(&As[k][ty*4]);
            float4 b4 = *reinterpret_cast<const float4*>(&Bs[k][tx*4]);
            float a[4] = {a4.x, a4.y, a4.z, a4.w};
            float b[4] = {b4.x, b4.y, b4.z, b4.w};
#pragma unroll
            for (int i = 0; i < 4; i++)
#pragma unroll
                for (int j = 0; j < 4; j++) acc[i][j] += a[i]*b[j];
        }
        __syncthreads();
    }
#pragma unroll
    for (int i = 0; i < 4; i++) {
        float4 v = make_float4(acc[i][0], acc[i][1], acc[i][2], acc[i][3]);
        *reinterpret_cast<float4*>(C + (size_t)(m0 + ty*4 + i)*LIN2 + n0 + tx*4) = v;
    }
    // per-CTA column partial sums for G2 BN stats (deterministic)
    {
        float s[4], q[4];
#pragma unroll
        for (int j = 0; j < 4; j++){
            s[j] = acc[0][j] + acc[1][j] + acc[2][j] + acc[3][j];
            q[j] = acc[0][j]*acc[0][j] + acc[1][j]*acc[1][j]
                 + acc[2][j]*acc[2][j] + acc[3][j]*acc[3][j];
        }
#pragma unroll
        for (int j = 0; j < 4; j++){ Ssum[ty][tx*4+j] = s[j]; Ssq[ty][tx*4+j] = q[j]; }
        __syncthreads();
        if (t < 64){
            float ss = 0.f, qq = 0.f;
#pragma unroll
            for (int m = 0; m < 16; m++){ ss += Ssum[m][t]; qq += Ssq[m][t]; }
            g_S2p[0][blockIdx.y][n0 + t] = ss;
            g_S2p[1][blockIdx.y][n0 + t] = qq;
        }
    }
}

// ---------------- final: reduce G2 stats in-block, BN2+ReLU+logits+softmax ----
__global__ void k_final_bn(const float* __restrict__ Wh3, const float* __restrict__ bh3,
                           const float* __restrict__ gamma, const float* __restrict__ beta,
                           float* __restrict__ out){
    __shared__ float sm[LIN2], sr[LIN2];
    int t = threadIdx.x;
    {
        int c = t;
        float s = 0.f, q = 0.f;
#pragma unroll 8
        for (int mb = 0; mb < 32; mb++){ s += g_S2p[0][mb][c]; q += g_S2p[1][mb][c]; }
        float m = s * (1.f/BATCHG);
        float v = q * (1.f/BATCHG) - m*m;
        sm[c] = m;
        sr[c] = rsqrtf(v + 1e-5f);
    }
    __syncthreads();
    int r = blockIdx.x*256 + t;
    if (r >= BATCHG) return;
    const float* h = g_G2 + (size_t)r * LIN2;
    float a0 = bh3[0], a1 = bh3[1], a2 = bh3[2];
    for (int k = 0; k < LIN2; k++) {
        float v = fmaxf((h[k] - sm[k]) * sr[k] * gamma[k] + beta[k], 0.f);
        a0 += v * Wh3[k*3+0];
        a1 += v * Wh3[k*3+1];
        a2 += v * Wh3[k*3+2];
    }
    float mx = fmaxf(a0, fmaxf(a1, a2));
    float e0 = expf(a0-mx), e1 = expf(a1-mx), e2 = expf(a2-mx);
    float inv = 1.f / (e0+e1+e2);
    out[r*3+0] = e0*inv; out[r*3+1] = e1*inv; out[r*3+2] = e2*inv;
}

// ---------------- launch ----------------
extern "C" void kernel_launch(void* const* d_in, const int* in_sizes, int n_in,
                              void* d_out, int out_size) {
    const float* x   = (const float*)d_in[0];
    const int*   ei  = (const int*)  d_in[1];
    const float* W1  = (const float*)d_in[2];
    const float* W2  = (const float*)d_in[4];
    const float* W3  = (const float*)d_in[6];
    const float* W4  = (const float*)d_in[8];
    const float* bb[4] = {(const float*)d_in[3], (const float*)d_in[5],
                          (const float*)d_in[7], (const float*)d_in[9]};
    const float* Wh1 = (const float*)d_in[10];
    const float* g1  = (const float*)d_in[12];
    const float* be1 = (const float*)d_in[13];
    const float* Wh2 = (const float*)d_in[14];
    const float* g2  = (const float*)d_in[16];
    const float* be2 = (const float*)d_in[17];
    const float* Wh3 = (const float*)d_in[18];
    const float* bh3 = (const float*)d_in[19];
    float* out = (float*)d_out;

    int E = in_sizes[1] / 2;
    const int* row = ei;
    const int* col = ei + E;

    float *hG1, *hG2;
    cudaGetSymbolAddress((void**)&hG1, g_G1);
    cudaGetSymbolAddress((void**)&hG2, g_G2);

    cudaFuncSetAttribute(mm_cheb,  cudaFuncAttributeMaxDynamicSharedMemorySize, CH_SMEM);
    cudaFuncSetAttribute(mm_feats, cudaFuncAttributeMaxDynamicSharedMemorySize, FT_SMEM);

    const int DPAD[4] = {128, 192, 256, 320};

    // merged prep (graph + weights + Wh1t + init H)
    k_prep_all<<<PB_TOT, 512>>>(x, row, col, W1, W2, W3, W4, Wh1);

    // 4 cheb layers (GEMM + fused MMA combine)
    for (int i = 0; i < 4; i++)
        mm_cheb<<<1024, 256, CH_SMEM>>>(i, DPAD[i], bb[i], 128 + 64*i);

    // MLP head
    mm_feats<<<dim3(4, 16, KSPLIT), 256, FT_SMEM>>>();
    k_redstats<<<64, 256>>>();
    gemm_s_bn<<<dim3(LIN2/64, BATCHG/64), 256>>>(hG1, Wh2, hG2, g1, be1);
    k_final_bn<<<(BATCHG + 255)/256, 256>>>(Wh3, bh3, g2, be2, out);
}

// round 15
// speedup vs baseline: 1.1709x; 1.1709x over previous
#include <cuda_runtime.h>
#include <cuda_fp16.h>

typedef unsigned short u16;
typedef unsigned int   u32;
typedef unsigned long long u64;

#define NODES 62
#define BATCHG 2048
#define NN (NODES*BATCHG)          // 126976
#define HROW 384                   // x:0-128 | x1:128-192 | x2:192-256 | x3:256-320 | x4:320-384
#define LINW 512
#define LIN2 256
#define KSPLIT 4
#define EPB 496

// ---------------- static device scratch ----------------
__device__ u16 g_Hh[(size_t)NN*HROW];          // H hi fp16
__device__ u16 g_Hl[(size_t)NN*HROW];          // H lo fp16 (only cols 0..127 ever read)
__device__ u16 g_Wt[4][5*192*64];              // cheb weights fp16, [blk][n][64]
__device__ u16 g_Wh1t[(size_t)248*512*64];     // Wh1 fp16 transposed blocks
__device__ u16 g_LA[4*4096];                   // [hl][kb][64 m][64 k] fp16 split of [L|L2]
__device__ float g_G1p[(size_t)KSPLIT*BATCHG*LINW];
__device__ float g_G1[BATCHG*LINW];
__device__ float g_G2[BATCHG*LIN2];
__device__ float g_S2p[2][32][LIN2];           // per-CTA G2 column partial sums
__device__ float g_L[62*64];
__device__ float g_L2[62*64];
__device__ float g_deg[64];
__device__ float g_mean[LINW];
__device__ float g_rstd[LINW];

// ---------------- helpers ----------------
__device__ __forceinline__ u32 smem_u32(const void* p){
    u32 a;
    asm("{ .reg .u64 t; cvta.to.shared.u64 t, %1; cvt.u32.u64 %0, t; }" : "=r"(a) : "l"(p));
    return a;
}
__device__ __forceinline__ void ldsm4(u32& r0,u32& r1,u32& r2,u32& r3,u32 addr){
    asm volatile("ldmatrix.sync.aligned.m8n8.x4.shared.b16 {%0,%1,%2,%3}, [%4];"
        : "=r"(r0),"=r"(r1),"=r"(r2),"=r"(r3) : "r"(addr));
}
__device__ __forceinline__ void mma_f16(float* d, const u32* a, const u32* b){
    asm volatile("mma.sync.aligned.m16n8k16.row.col.f32.f16.f16.f32 "
        "{%0,%1,%2,%3}, {%4,%5,%6,%7}, {%8,%9}, {%0,%1,%2,%3};"
        : "+f"(d[0]),"+f"(d[1]),"+f"(d[2]),"+f"(d[3])
        : "r"(a[0]),"r"(a[1]),"r"(a[2]),"r"(a[3]), "r"(b[0]),"r"(b[1]));
}
__device__ __forceinline__ u32 swz(u32 bo){ return bo ^ ((bo >> 3) & 0x70); }
__device__ __forceinline__ void splith(float v, u16& h, u16& l){
    __half hh = __float2half(v);
    __half ll = __float2half(v - __half2float(hh));
    h = *reinterpret_cast<u16*>(&hh);
    l = *reinterpret_cast<u16*>(&ll);
}
__device__ __forceinline__ u16 h16(float v){
    __half hh = __float2half(v);
    return *reinterpret_cast<u16*>(&hh);
}
__device__ __forceinline__ void cpa16(u32 dst, const void* src){
    asm volatile("cp.async.cg.shared.global [%0], [%1], 16;" :: "r"(dst), "l"(src));
}
__device__ __forceinline__ void cpa_commit(){ asm volatile("cp.async.commit_group;"); }
template<int N> __device__ __forceinline__ void cpa_wait(){
    asm volatile("cp.async.wait_group %0;" :: "n"(N));
}

// ---------------- merged prep kernel: graphprep | prepW | prepWh1t | init_H ----
#define PB_W    1
#define PB_WH1  337
#define PB_INIT 2321
#define PB_TOT  6289

__global__ void k_prep_all(const float* __restrict__ x,
                           const int* __restrict__ row, const int* __restrict__ col,
                           const float* __restrict__ W0, const float* __restrict__ W1,
                           const float* __restrict__ W2, const float* __restrict__ W3,
                           const float* __restrict__ Wh1)
{
    int b = blockIdx.x;
    int tid = threadIdx.x;   // 512

    if (b == 0){
        int t = tid;
        if (t < 64) g_deg[t] = 0.f;
        for (int i = t; i < 62*64; i += 512){ g_L[i] = 0.f; g_L2[i] = 0.f; }
        __syncthreads();
        if (t < EPB) atomicAdd(&g_deg[row[t]], 1.0f);
        __syncthreads();
        if (t < EPB){
            int r = row[t], c = col[t];
            float w = -rsqrtf(g_deg[r]) * rsqrtf(g_deg[c]);
            atomicAdd(&g_L[r*64 + c], w);
        }
        __syncthreads();
        for (int i = t; i < 62*64; i += 512){
            int r = i >> 6, j = i & 63;
            float s = 0.f;
            if (j < 62)
                for (int m = 0; m < 62; m++) s += g_L[r*64+m] * g_L[m*64+j];
            g_L2[i] = s;
        }
        __syncthreads();
        for (int i = t; i < 8192; i += 512){
            int kb = i >> 12, rem = i & 4095;
            int m = rem >> 6, k = rem & 63;
            float val = 0.f;
            if (m < 62 && k < 62) val = kb ? g_L2[m*64+k] : g_L[m*64+k];
            u16 h, l; splith(val, h, l);
            g_LA[kb*4096 + rem] = h;
            g_LA[8192 + kb*4096 + rem] = l;
        }
    } else if (b < PB_WH1){
        int t = (b - PB_W)*512 + tid;
        if (t >= 172032) return;
        int layer, base, dreal;
        if (t < 24576)       { layer=0; base=0;      dreal=128; }
        else if (t < 61440)  { layer=1; base=24576;  dreal=190; }
        else if (t < 110592) { layer=2; base=61440;  dreal=252; }
        else                 { layer=3; base=110592; dreal=314; }
        const float* W = (layer==0) ? W0 : (layer==1) ? W1 : (layer==2) ? W2 : W3;
        int idx = t - base;
        int n = idx % 192, k = idx / 192;
        int ch = n >> 6, j = n & 63;
        float val = 0.f;
        int rr = -1;
        if (k < 128) rr = k;
        else { int q = k - 128; int chunk = q >> 6, w = q & 63; if (w < 62) rr = 128 + chunk*62 + w; }
        if (rr >= 0 && rr < dreal && j < 62) {
            const float* Wp0 = W;
            const float* Wp1 = W + (size_t)dreal*62;
            const float* Wp2 = W + (size_t)2*dreal*62;
            if (ch == 0)      val = Wp0[rr*62+j] - Wp2[rr*62+j];
            else if (ch == 1) val = Wp1[rr*62+j];
            else              val = 2.f * Wp2[rr*62+j];
        }
        int blk = k >> 6, kk = k & 63;
        g_Wt[layer][(size_t)blk*12288 + n*64 + kk] = h16(val);
    } else if (b < PB_INIT){
        int idx = (b - PB_WH1)*512 + tid;
        int n = idx & 511;
        int q = idx >> 9;
        int blk = q >> 3, c8 = (q & 7) * 8;
        union { u16 u[8]; uint4 v; } H;
#pragma unroll
        for (int i = 0; i < 8; i++){
            int k = blk*64 + c8 + i;
            int node = k >> 8, cc = k & 255, ch = cc >> 6, w = cc & 63;
            float val = 0.f;
            if (w < 62) val = Wh1[((size_t)(node*248 + ch*62 + w))*LINW + n];
            H.u[i] = h16(val);
        }
        *(uint4*)(g_Wh1t + ((size_t)blk*512 + n)*64 + c8) = H.v;
    } else {
        size_t idx = (size_t)(b - PB_INIT)*512 + tid;
        size_t r = idx >> 4;
        int c8 = ((int)idx & 15) * 8;
        float4 a = *(const float4*)(x + r*128 + c8);
        float4 bb4 = *(const float4*)(x + r*128 + c8 + 4);
        float v[8] = {a.x,a.y,a.z,a.w,bb4.x,bb4.y,bb4.z,bb4.w};
        union { u16 u[8]; uint4 q; } H, L;
#pragma unroll
        for (int i = 0; i < 8; i++) splith(v[i], H.u[i], L.u[i]);
        *(uint4*)(g_Hh + r*HROW + c8) = H.q;
        *(uint4*)(g_Hl + r*HROW + c8) = L.q;
    }
}

// ---------------- mma.sync cheb GEMM + MMA combine epilogue ----------------
// CTA: 128 M-rows (124 used), N=192, k-chunks of 64, 2-stage cp.async, 2 CTAs/SM.
// B ldsm'd ONCE per ks (kept live) and reused across hi/lo A passes.
#define CH_A_HI 0
#define CH_A_LO 16384
#define CH_B    32768
#define CH_BUF  57344
#define CH_ST   0
#define CH_BT   32768
#define CH_AL   65536
#define CH_SMEM (2*CH_BUF)   // 114688

__global__ __launch_bounds__(256,2) void mm_cheb(int layer, int Kdim,
                                                 const float* __restrict__ bias, int cbase)
{
    extern __shared__ char smem[];
    const u32 sb = smem_u32(smem);
    const int t = threadIdx.x, wid = t >> 5, l = t & 31;
    const int wm = (wid & 1) * 64, wn = (wid >> 1) * 48;
    const int m0 = blockIdx.x * 124;
    const int nch = Kdim >> 6;
    const u16* Bw = g_Wt[layer];

    float acc[4][6][4];
#pragma unroll
    for (int a = 0; a < 4; a++)
#pragma unroll
        for (int b = 0; b < 6; b++)
#pragma unroll
            for (int c = 0; c < 4; c++) acc[a][b][c] = 0.f;

    auto stage = [&](int c){
        u32 bufb = sb + (c & 1) * CH_BUF;
        int k0 = c << 6;
        bool useLo = (c < 2);
        for (int i = t; i < 1024; i += 256){
            int r = i >> 3, cc = i & 7;
            int gr = m0 + r; if (gr > NN-1) gr = NN-1;
            size_t go = (size_t)gr*HROW + k0 + cc*8;
            u32 bo = swz((u32)(r*128 + cc*16));
            cpa16(bufb + CH_A_HI + bo, g_Hh + go);
            if (useLo) cpa16(bufb + CH_A_LO + bo, g_Hl + go);
        }
        const u16* pb = Bw + (size_t)c*12288;
        for (int i = t; i < 1536; i += 256){
            int r = i >> 3, cc = i & 7;
            u32 bo = swz((u32)(r*128 + cc*16));
            cpa16(bufb + CH_B + bo, pb + r*64 + cc*8);
        }
        cpa_commit();
    };

    stage(0);
    for (int c = 0; c < nch; c++){
        if (c+1 < nch) { stage(c+1); cpa_wait<1>(); }
        else cpa_wait<0>();
        __syncthreads();
        u32 bufb = sb + (c & 1) * CH_BUF;
        bool useLo = (c < 2);
#pragma unroll
        for (int ks = 0; ks < 4; ks++){
            int arow = wm + (l & 7) + ((l >> 3) & 1) * 8;
            int acol = ks*32 + ((l >> 4) & 1) * 16;
            int brow = wn + (l & 7) + ((l >> 4) & 1) * 8;
            int bcol = ks*32 + ((l >> 3) & 1) * 16;
            // B once per ks, kept live across hi/lo passes
            u32 bw4[3][4];
#pragma unroll
            for (int bi = 0; bi < 3; bi++){
                u32 bo = swz((u32)((brow + bi*16)*128 + bcol));
                ldsm4(bw4[bi][0],bw4[bi][1],bw4[bi][2],bw4[bi][3], bufb + CH_B + bo);
            }
            // hi pass: stream A one mi-tile at a time
#pragma unroll
            for (int mi = 0; mi < 4; mi++){
                u32 aa[4];
                u32 bo = swz((u32)((arow + mi*16)*128 + acol));
                ldsm4(aa[0],aa[1],aa[2],aa[3], bufb + CH_A_HI + bo);
#pragma unroll
                for (int bi = 0; bi < 3; bi++){
                    mma_f16(acc[mi][2*bi],   aa, &bw4[bi][0]);
                    mma_f16(acc[mi][2*bi+1], aa, &bw4[bi][2]);
                }
            }
            // lo pass (x chunks only), B regs reused
            if (useLo){
#pragma unroll
                for (int mi = 0; mi < 4; mi++){
                    u32 aa[4];
                    u32 bo = swz((u32)((arow + mi*16)*128 + acol));
                    ldsm4(aa[0],aa[1],aa[2],aa[3], bufb + CH_A_LO + bo);
#pragma unroll
                    for (int bi = 0; bi < 3; bi++){
                        mma_f16(acc[mi][2*bi],   aa, &bw4[bi][0]);
                        mma_f16(acc[mi][2*bi+1], aa, &bw4[bi][2]);
                    }
                }
            }
        }
        __syncthreads();
    }

    // ---- combine epilogue: out = P0 + [L|L2]@[P1;P2], via MMA ----
    {
        int i = t;
        int g = i >> 7, kb = (i >> 6) & 1, feat = i & 63;
        u32 bo = CH_BT + g*16384 + kb*8192 + swz((u32)(feat*128 + 124));
        *(u32*)(smem + bo) = 0u;
    }
    for (int i = t; i < 2048; i += 256){
        int blk = i >> 9, rem = i & 511;
        int r = rem >> 3, cc = rem & 7;
        u32 bo = swz((u32)(r*128 + cc*16));
        *(float4*)(smem + CH_AL + blk*8192 + bo) = *(const float4*)(g_LA + blk*4096 + r*64 + cc*8);
    }
    __syncthreads();
    {
        float* stg = (float*)(smem + CH_ST);
#pragma unroll
        for (int mi = 0; mi < 4; mi++)
#pragma unroll
            for (int ni = 0; ni < 6; ni++)
#pragma unroll
                for (int rp = 0; rp < 4; rp += 2){
                    int row = wm + mi*16 + (l>>2) + (rp ? 8 : 0);
                    int col = wn + ni*8 + (l&3)*2;
                    float v0 = acc[mi][ni][rp], v1 = acc[mi][ni][rp+1];
                    if (col < 64){
                        *(float2*)&stg[row*64 + col] = make_float2(v0, v1);
                    } else if (row < 124){
                        int g = (row >= 62) ? 1 : 0;
                        int node = row - g*62;
                        int kbB = (col >= 128) ? 1 : 0;
                        int feat = col - (kbB ? 128 : 64);
                        u32 b0 = CH_BT + g*16384 + kbB*8192 + swz((u32)(feat*128 + node*2));
                        u32 b1 = CH_BT + g*16384 + kbB*8192 + swz((u32)((feat+1)*128 + node*2));
                        *(u16*)(smem + b0) = h16(v0);
                        *(u16*)(smem + b1) = h16(v1);
                    }
                }
    }
    __syncthreads();
    {
        int g = wid >> 2, mt = wid & 3;
        float a2[8][4];
#pragma unroll
        for (int j = 0; j < 8; j++)
#pragma unroll
            for (int r = 0; r < 4; r++) a2[j][r] = 0.f;
#pragma unroll
        for (int kb = 0; kb < 2; kb++)
#pragma unroll
            for (int k16 = 0; k16 < 4; k16++){
                u32 Ah[4], Al4[4];
                u32 boA = swz((u32)((mt*16 + (l&7) + ((l>>3)&1)*8)*128 + k16*32 + ((l>>4)&1)*16));
                ldsm4(Ah[0],Ah[1],Ah[2],Ah[3],     sb + CH_AL + kb*8192 + boA);
                ldsm4(Al4[0],Al4[1],Al4[2],Al4[3], sb + CH_AL + 16384 + kb*8192 + boA);
#pragma unroll
                for (int np = 0; np < 4; np++){
                    u32 Bw4[4];
                    u32 boB = swz((u32)((np*16 + (l&7) + ((l>>4)&1)*8)*128 + k16*32 + ((l>>3)&1)*16));
                    ldsm4(Bw4[0],Bw4[1],Bw4[2],Bw4[3], sb + CH_BT + g*16384 + kb*8192 + boB);
                    mma_f16(a2[2*np],   Ah,  &Bw4[0]);
                    mma_f16(a2[2*np],   Al4, &Bw4[0]);
                    mma_f16(a2[2*np+1], Ah,  &Bw4[2]);
                    mma_f16(a2[2*np+1], Al4, &Bw4[2]);
                }
            }
        float* stg = (float*)(smem + CH_ST);
        size_t hrow0 = ((size_t)(blockIdx.x*2 + g)) * 62;
#pragma unroll
        for (int j = 0; j < 8; j++)
#pragma unroll
            for (int rp = 0; rp < 4; rp += 2){
                int node = mt*16 + (l>>2) + (rp ? 8 : 0);
                if (node >= 62) continue;
                int col = j*8 + (l&3)*2;
                float v0 = a2[j][rp]   + stg[(g*62+node)*64 + col];
                float v1 = a2[j][rp+1] + stg[(g*62+node)*64 + col+1];
                v0 = (col   < 62) ? fmaxf(v0 + bias[col],   0.f) : 0.f;
                v1 = (col+1 < 62) ? fmaxf(v1 + bias[col+1], 0.f) : 0.f;
                size_t off = (hrow0 + node)*HROW + cbase + col;
                *(u32*)(g_Hh + off) = (u32)h16(v0) | ((u32)h16(v1) << 16);
            }
    }
}

// ---------------- mma.sync feats GEMM: A-hi only, N-tile 256, split-K=4 --------
// R13 config: 3-stage cp.async (.cg), 1 CTA/SM, single __syncthreads/iter.
#define FT_A    0
#define FT_B    16384
#define FT_BUF  49152
#define FT_SMEM (3*FT_BUF)   // 147456

__global__ __launch_bounds__(256,1) void mm_feats()
{
    extern __shared__ char smem[];
    const u32 sb = smem_u32(smem);
    const int t = threadIdx.x, wid = t >> 5, l = t & 31;
    const int wm = (wid & 1) * 64, wn = (wid >> 1) * 64;
    const int n0 = blockIdx.x * 256;
    const int m0 = blockIdx.y * 128;
    const int part = blockIdx.z;
    const int cbeg = part * 62;

    float acc[4][8][4];
#pragma unroll
    for (int a = 0; a < 4; a++)
#pragma unroll
        for (int b = 0; b < 8; b++)
#pragma unroll
            for (int c = 0; c < 4; c++) acc[a][b][c] = 0.f;

    auto stage = [&](int cl){
        u32 bufb = sb + (cl % 3) * FT_BUF;
        int c = cbeg + cl;
        int node = c >> 2, col0 = 128 + ((c & 3) << 6);
        for (int i = t; i < 512; i += 256){
            int r = i >> 2, cc = (i & 3) * 2;
            size_t go = ((size_t)(m0 + r)*62 + node)*HROW + col0 + cc*8;
            cpa16(bufb + FT_A + swz((u32)(r*128 + cc*16)), g_Hh + go);
            cpa16(bufb + FT_A + swz((u32)(r*128 + (cc+1)*16)), g_Hh + go + 8);
        }
        const u16* pb = g_Wh1t + ((size_t)c*512 + n0)*64;
        for (int i = t; i < 2048; i += 256){
            int r = i >> 3, cc = i & 7;
            cpa16(bufb + FT_B + swz((u32)(r*128 + cc*16)), pb + r*64 + cc*8);
        }
        cpa_commit();
    };

    stage(0); stage(1);
    for (int cl = 0; cl < 62; cl++){
        if (cl+1 < 62) cpa_wait<1>();
        else cpa_wait<0>();
        __syncthreads();
        if (cl+2 < 62) stage(cl+2);
        u32 bufb = sb + (cl % 3) * FT_BUF;
#pragma unroll
        for (int ks = 0; ks < 4; ks++){
            u32 ah[4][4];
            int arow = wm + (l & 7) + ((l >> 3) & 1) * 8;
            int acol = ks*32 + ((l >> 4) & 1) * 16;
#pragma unroll
            for (int mi = 0; mi < 4; mi++){
                u32 bo = swz((u32)((arow + mi*16)*128 + acol));
                ldsm4(ah[mi][0],ah[mi][1],ah[mi][2],ah[mi][3], bufb + FT_A + bo);
            }
            u32 bw[4][4];
            int brow = wn + (l & 7) + ((l >> 4) & 1) * 8;
            int bcol = ks*32 + ((l >> 3) & 1) * 16;
#pragma unroll
            for (int bi = 0; bi < 4; bi++){
                u32 bo = swz((u32)((brow + bi*16)*128 + bcol));
                ldsm4(bw[bi][0],bw[bi][1],bw[bi][2],bw[bi][3], bufb + FT_B + bo);
            }
#pragma unroll
            for (int mi = 0; mi < 4; mi++)
#pragma unroll
                for (int bi = 0; bi < 4; bi++){
                    mma_f16(acc[mi][2*bi],   ah[mi], &bw[bi][0]);
                    mma_f16(acc[mi][2*bi+1], ah[mi], &bw[bi][2]);
                }
        }
    }

    float* outp = g_G1p + (size_t)part*BATCHG*LINW;
#pragma unroll
    for (int mi = 0; mi < 4; mi++)
#pragma unroll
        for (int ni = 0; ni < 8; ni++){
            int row = m0 + wm + mi*16 + (l >> 2);
            int col = n0 + wn + ni*8 + (l & 3)*2;
            *(float2*)&outp[(size_t)row*LINW + col]     = make_float2(acc[mi][ni][0], acc[mi][ni][1]);
            *(float2*)&outp[(size_t)(row+8)*LINW + col] = make_float2(acc[mi][ni][2], acc[mi][ni][3]);
        }
}

// ---------------- fused split-K reduce + BN1 stats ----------------
__global__ void k_redstats(){
    int c0 = blockIdx.x * 8;
    int t = threadIdx.x;
    int c = c0 + (t & 7);
    float s = 0.f, sq = 0.f;
    for (int r = (t >> 3); r < BATCHG; r += 32){
        size_t off = (size_t)r*LINW + c;
        float v = g_G1p[off]
                + g_G1p[(size_t)BATCHG*LINW + off]
                + g_G1p[(size_t)2*BATCHG*LINW + off]
                + g_G1p[(size_t)3*BATCHG*LINW + off];
        g_G1[off] = v;
        s += v; sq += v*v;
    }
    __shared__ float sh[256], sh2[256];
    sh[t] = s; sh2[t] = sq; __syncthreads();
    for (int o = 128; o >= 8; o >>= 1){
        if (t < o){ sh[t] += sh[t+o]; sh2[t] += sh2[t+o]; }
        __syncthreads();
    }
    if (t < 8){
        float m = sh[t] * (1.f/BATCHG);
        float v = sh2[t] * (1.f/BATCHG) - m*m;
        g_mean[c0+t] = m;
        g_rstd[c0+t] = rsqrtf(v + 1e-5f);
    }
}

// ---------------- SIMT fp32 GEMM for Wh2, BN1+ReLU fused, G2 partial stats ----
__global__ void gemm_s_bn(const float* __restrict__ A, const float* __restrict__ B,
                          float* __restrict__ C,
                          const float* __restrict__ gamma, const float* __restrict__ beta)
{
    __shared__ float As[16][68];
    __shared__ float Bs[16][64];
    __shared__ float Ssum[16][64], Ssq[16][64];
    int t = threadIdx.x;
    int m0 = blockIdx.y * 64, n0 = blockIdx.x * 64;
    int ty = t >> 4, tx = t & 15;
    int am = t >> 2, ak = (t & 3) * 4;
    int bk = t >> 4, bn = (t & 15) * 4;
    float acc[4][4];
#pragma unroll
    for (int i = 0; i < 4; i++)
#pragma unroll
        for (int j = 0; j < 4; j++) acc[i][j] = 0.f;
    for (int k0 = 0; k0 < LINW; k0 += 16) {
        float4 av = *reinterpret_cast<const float4*>(A + (size_t)(m0+am)*LINW + k0 + ak);
        float va[4] = {av.x, av.y, av.z, av.w};
#pragma unroll
        for (int q = 0; q < 4; q++){
            int k = k0 + ak + q;
            va[q] = fmaxf((va[q] - g_mean[k]) * g_rstd[k] * gamma[k] + beta[k], 0.f);
            As[ak+q][am] = va[q];
        }
        float4 bv = *reinterpret_cast<const float4*>(B + (size_t)(k0+bk)*LIN2 + n0 + bn);
        *reinterpret_cast<float4*>(&Bs[bk][bn]) = bv;
        __syncthreads();
#pragma unroll
        for (int k = 0; k < 16; k++) {
            float4 a4 = *reinterpret_cast<const float4*>(&As[k][ty*4]);
            float4 b4 = *reinterpret_cast<const float4*>(&Bs[k][tx*4]);
            float a[4] = {a4.x, a4.y, a4.z, a4.w};
            float b[4] = {b4.x, b4.y, b4.z, b4.w};
#pragma unroll
            for (int i = 0; i < 4; i++)
#pragma unroll
                for (int j = 0; j < 4; j++) acc[i][j] += a[i]*b[j];
        }
        __syncthreads();
    }
#pragma unroll
    for (int i = 0; i < 4; i++) {
        float4 v = make_float4(acc[i][0], acc[i][1], acc[i][2], acc[i][3]);
        *reinterpret_cast<float4*>(C + (size_t)(m0 + ty*4 + i)*LIN2 + n0 + tx*4) = v;
    }
    {
        float s[4], q[4];
#pragma unroll
        for (int j = 0; j < 4; j++){
            s[j] = acc[0][j] + acc[1][j] + acc[2][j] + acc[3][j];
            q[j] = acc[0][j]*acc[0][j] + acc[1][j]*acc[1][j]
                 + acc[2][j]*acc[2][j] + acc[3][j]*acc[3][j];
        }
#pragma unroll
        for (int j = 0; j < 4; j++){ Ssum[ty][tx*4+j] = s[j]; Ssq[ty][tx*4+j] = q[j]; }
        __syncthreads();
        if (t < 64){
            float ss = 0.f, qq = 0.f;
#pragma unroll
            for (int m = 0; m < 16; m++){ ss += Ssum[m][t]; qq += Ssq[m][t]; }
            g_S2p[0][blockIdx.y][n0 + t] = ss;
            g_S2p[1][blockIdx.y][n0 + t] = qq;
        }
    }
}

// ---------------- final: reduce G2 stats in-block, BN2+ReLU+logits+softmax ----
__global__ void k_final_bn(const float* __restrict__ Wh3, const float* __restrict__ bh3,
                           const float* __restrict__ gamma, const float* __restrict__ beta,
                           float* __restrict__ out){
    __shared__ float sm[LIN2], sr[LIN2];
    int t = threadIdx.x;
    {
        int c = t;
        float s = 0.f, q = 0.f;
#pragma unroll 8
        for (int mb = 0; mb < 32; mb++){ s += g_S2p[0][mb][c]; q += g_S2p[1][mb][c]; }
        float m = s * (1.f/BATCHG);
        float v = q * (1.f/BATCHG) - m*m;
        sm[c] = m;
        sr[c] = rsqrtf(v + 1e-5f);
    }
    __syncthreads();
    int r = blockIdx.x*256 + t;
    if (r >= BATCHG) return;
    const float* h = g_G2 + (size_t)r * LIN2;
    float a0 = bh3[0], a1 = bh3[1], a2 = bh3[2];
    for (int k = 0; k < LIN2; k++) {
        float v = fmaxf((h[k] - sm[k]) * sr[k] * gamma[k] + beta[k], 0.f);
        a0 += v * Wh3[k*3+0];
        a1 += v * Wh3[k*3+1];
        a2 += v * Wh3[k*3+2];
    }
    float mx = fmaxf(a0, fmaxf(a1, a2));
    float e0 = expf(a0-mx), e1 = expf(a1-mx), e2 = expf(a2-mx);
    float inv = 1.f / (e0+e1+e2);
    out[r*3+0] = e0*inv; out[r*3+1] = e1*inv; out[r*3+2] = e2*inv;
}

// ---------------- launch ----------------
extern "C" void kernel_launch(void* const* d_in, const int* in_sizes, int n_in,
                              void* d_out, int out_size) {
    const float* x   = (const float*)d_in[0];
    const int*   ei  = (const int*)  d_in[1];
    const float* W1  = (const float*)d_in[2];
    const float* W2  = (const float*)d_in[4];
    const float* W3  = (const float*)d_in[6];
    const float* W4  = (const float*)d_in[8];
    const float* bb[4] = {(const float*)d_in[3], (const float*)d_in[5],
                          (const float*)d_in[7], (const float*)d_in[9]};
    const float* Wh1 = (const float*)d_in[10];
    const float* g1  = (const float*)d_in[12];
    const float* be1 = (const float*)d_in[13];
    const float* Wh2 = (const float*)d_in[14];
    const float* g2  = (const float*)d_in[16];
    const float* be2 = (const float*)d_in[17];
    const float* Wh3 = (const float*)d_in[18];
    const float* bh3 = (const float*)d_in[19];
    float* out = (float*)d_out;

    int E = in_sizes[1] / 2;
    const int* row = ei;
    const int* col = ei + E;

    float *hG1, *hG2;
    cudaGetSymbolAddress((void**)&hG1, g_G1);
    cudaGetSymbolAddress((void**)&hG2, g_G2);

    cudaFuncSetAttribute(mm_cheb,  cudaFuncAttributeMaxDynamicSharedMemorySize, CH_SMEM);
    cudaFuncSetAttribute(mm_feats, cudaFuncAttributeMaxDynamicSharedMemorySize, FT_SMEM);

    const int DPAD[4] = {128, 192, 256, 320};

    // merged prep (graph + weights + Wh1t + init H)
    k_prep_all<<<PB_TOT, 512>>>(x, row, col, W1, W2, W3, W4, Wh1);

    // 4 cheb layers (GEMM + fused MMA combine)
    for (int i = 0; i < 4; i++)
        mm_cheb<<<1024, 256, CH_SMEM>>>(i, DPAD[i], bb[i], 128 + 64*i);

    // MLP head
    mm_feats<<<dim3(2, 16, KSPLIT), 256, FT_SMEM>>>();
    k_redstats<<<64, 256>>>();
    gemm_s_bn<<<dim3(LIN2/64, BATCHG/64), 256>>>(hG1, Wh2, hG2, g1, be1);
    k_final_bn<<<(BATCHG + 255)/256, 256>>>(Wh3, bh3, g2, be2, out);
}

// round 16
// speedup vs baseline: 1.2293x; 1.0498x over previous
#include <cuda_runtime.h>
#include <cuda_fp16.h>

typedef unsigned short u16;
typedef unsigned int   u32;
typedef unsigned long long u64;

#define NODES 62
#define BATCHG 2048
#define NN (NODES*BATCHG)          // 126976
#define HROW 384                   // x:0-128 | x1:128-192 | x2:192-256 | x3:256-320 | x4:320-384
#define LINW 512
#define LIN2 256
#define KSPLIT 4
#define EPB 496

// ---------------- static device scratch ----------------
__device__ u16 g_Hh[(size_t)NN*HROW];          // H hi fp16
__device__ u16 g_Hl[(size_t)NN*HROW];          // H lo fp16 (only cols 0..127 of layer-0 read)
__device__ u16 g_Wt[4][5*192*64];              // cheb weights fp16, [blk][n][64]
__device__ u16 g_Wh1t[(size_t)248*512*64];     // Wh1 fp16 transposed blocks
__device__ u16 g_LA[4*4096];                   // [hl][kb][64 m][64 k] fp16 split of [L|L2]
__device__ float g_G1p[(size_t)KSPLIT*BATCHG*LINW];
__device__ float g_G1[BATCHG*LINW];
__device__ float g_G2[BATCHG*LIN2];
__device__ float g_S2p[2][32][LIN2];           // per-CTA G2 column partial sums
__device__ float g_L[62*64];
__device__ float g_L2[62*64];
__device__ float g_deg[64];
__device__ float g_mean[LINW];
__device__ float g_rstd[LINW];

// ---------------- helpers ----------------
__device__ __forceinline__ u32 smem_u32(const void* p){
    u32 a;
    asm("{ .reg .u64 t; cvta.to.shared.u64 t, %1; cvt.u32.u64 %0, t; }" : "=r"(a) : "l"(p));
    return a;
}
__device__ __forceinline__ void ldsm4(u32& r0,u32& r1,u32& r2,u32& r3,u32 addr){
    asm volatile("ldmatrix.sync.aligned.m8n8.x4.shared.b16 {%0,%1,%2,%3}, [%4];"
        : "=r"(r0),"=r"(r1),"=r"(r2),"=r"(r3) : "r"(addr));
}
__device__ __forceinline__ void mma_f16(float* d, const u32* a, const u32* b){
    asm volatile("mma.sync.aligned.m16n8k16.row.col.f32.f16.f16.f32 "
        "{%0,%1,%2,%3}, {%4,%5,%6,%7}, {%8,%9}, {%0,%1,%2,%3};"
        : "+f"(d[0]),"+f"(d[1]),"+f"(d[2]),"+f"(d[3])
        : "r"(a[0]),"r"(a[1]),"r"(a[2]),"r"(a[3]), "r"(b[0]),"r"(b[1]));
}
__device__ __forceinline__ u32 swz(u32 bo){ return bo ^ ((bo >> 3) & 0x70); }
__device__ __forceinline__ void splith(float v, u16& h, u16& l){
    __half hh = __float2half(v);
    __half ll = __float2half(v - __half2float(hh));
    h = *reinterpret_cast<u16*>(&hh);
    l = *reinterpret_cast<u16*>(&ll);
}
__device__ __forceinline__ u16 h16(float v){
    __half hh = __float2half(v);
    return *reinterpret_cast<u16*>(&hh);
}
__device__ __forceinline__ void cpa16(u32 dst, const void* src){
    asm volatile("cp.async.cg.shared.global [%0], [%1], 16;" :: "r"(dst), "l"(src));
}
__device__ __forceinline__ void cpa_commit(){ asm volatile("cp.async.commit_group;"); }
template<int N> __device__ __forceinline__ void cpa_wait(){
    asm volatile("cp.async.wait_group %0;" :: "n"(N));
}

// ---------------- merged prep kernel: graphprep | prepW | prepWh1t | init_H ----
#define PB_W    1
#define PB_WH1  337
#define PB_INIT 2321
#define PB_TOT  6289

__global__ void k_prep_all(const float* __restrict__ x,
                           const int* __restrict__ row, const int* __restrict__ col,
                           const float* __restrict__ W0, const float* __restrict__ W1,
                           const float* __restrict__ W2, const float* __restrict__ W3,
                           const float* __restrict__ Wh1)
{
    int b = blockIdx.x;
    int tid = threadIdx.x;   // 512

    if (b == 0){
        int t = tid;
        if (t < 64) g_deg[t] = 0.f;
        for (int i = t; i < 62*64; i += 512){ g_L[i] = 0.f; g_L2[i] = 0.f; }
        __syncthreads();
        if (t < EPB) atomicAdd(&g_deg[row[t]], 1.0f);
        __syncthreads();
        if (t < EPB){
            int r = row[t], c = col[t];
            float w = -rsqrtf(g_deg[r]) * rsqrtf(g_deg[c]);
            atomicAdd(&g_L[r*64 + c], w);
        }
        __syncthreads();
        for (int i = t; i < 62*64; i += 512){
            int r = i >> 6, j = i & 63;
            float s = 0.f;
            if (j < 62)
                for (int m = 0; m < 62; m++) s += g_L[r*64+m] * g_L[m*64+j];
            g_L2[i] = s;
        }
        __syncthreads();
        for (int i = t; i < 8192; i += 512){
            int kb = i >> 12, rem = i & 4095;
            int m = rem >> 6, k = rem & 63;
            float val = 0.f;
            if (m < 62 && k < 62) val = kb ? g_L2[m*64+k] : g_L[m*64+k];
            u16 h, l; splith(val, h, l);
            g_LA[kb*4096 + rem] = h;
            g_LA[8192 + kb*4096 + rem] = l;
        }
    } else if (b < PB_WH1){
        int t = (b - PB_W)*512 + tid;
        if (t >= 172032) return;
        int layer, base, dreal;
        if (t < 24576)       { layer=0; base=0;      dreal=128; }
        else if (t < 61440)  { layer=1; base=24576;  dreal=190; }
        else if (t < 110592) { layer=2; base=61440;  dreal=252; }
        else                 { layer=3; base=110592; dreal=314; }
        const float* W = (layer==0) ? W0 : (layer==1) ? W1 : (layer==2) ? W2 : W3;
        int idx = t - base;
        int n = idx % 192, k = idx / 192;
        int ch = n >> 6, j = n & 63;
        float val = 0.f;
        int rr = -1;
        if (k < 128) rr = k;
        else { int q = k - 128; int chunk = q >> 6, w = q & 63; if (w < 62) rr = 128 + chunk*62 + w; }
        if (rr >= 0 && rr < dreal && j < 62) {
            const float* Wp0 = W;
            const float* Wp1 = W + (size_t)dreal*62;
            const float* Wp2 = W + (size_t)2*dreal*62;
            if (ch == 0)      val = Wp0[rr*62+j] - Wp2[rr*62+j];
            else if (ch == 1) val = Wp1[rr*62+j];
            else              val = 2.f * Wp2[rr*62+j];
        }
        int blk = k >> 6, kk = k & 63;
        g_Wt[layer][(size_t)blk*12288 + n*64 + kk] = h16(val);
    } else if (b < PB_INIT){
        int idx = (b - PB_WH1)*512 + tid;
        int n = idx & 511;
        int q = idx >> 9;
        int blk = q >> 3, c8 = (q & 7) * 8;
        union { u16 u[8]; uint4 v; } H;
#pragma unroll
        for (int i = 0; i < 8; i++){
            int k = blk*64 + c8 + i;
            int node = k >> 8, cc = k & 255, ch = cc >> 6, w = cc & 63;
            float val = 0.f;
            if (w < 62) val = Wh1[((size_t)(node*248 + ch*62 + w))*LINW + n];
            H.u[i] = h16(val);
        }
        *(uint4*)(g_Wh1t + ((size_t)blk*512 + n)*64 + c8) = H.v;
    } else {
        size_t idx = (size_t)(b - PB_INIT)*512 + tid;
        size_t r = idx >> 4;
        int c8 = ((int)idx & 15) * 8;
        float4 a = *(const float4*)(x + r*128 + c8);
        float4 bb4 = *(const float4*)(x + r*128 + c8 + 4);
        float v[8] = {a.x,a.y,a.z,a.w,bb4.x,bb4.y,bb4.z,bb4.w};
        union { u16 u[8]; uint4 q; } H, L;
#pragma unroll
        for (int i = 0; i < 8; i++) splith(v[i], H.u[i], L.u[i]);
        *(uint4*)(g_Hh + r*HROW + c8) = H.q;
        *(uint4*)(g_Hl + r*HROW + c8) = L.q;
    }
}

// ---------------- mma.sync cheb GEMM + MMA combine epilogue ----------------
// CTA: 128 M-rows (124 used), N=192, k-chunks of 64, 2-stage cp.async, 2 CTAs/SM.
// B ldsm'd ONCE per ks, reused across hi/lo. A-lo only in layer 0 (x exact path).
#define CH_A_HI 0
#define CH_A_LO 16384
#define CH_B    32768
#define CH_BUF  57344
#define CH_ST   0
#define CH_BT   32768
#define CH_AL   65536
#define CH_SMEM (2*CH_BUF)   // 114688

__global__ __launch_bounds__(256,2) void mm_cheb(int layer, int Kdim,
                                                 const float* __restrict__ bias, int cbase)
{
    extern __shared__ char smem[];
    const u32 sb = smem_u32(smem);
    const int t = threadIdx.x, wid = t >> 5, l = t & 31;
    const int wm = (wid & 1) * 64, wn = (wid >> 1) * 48;
    const int m0 = blockIdx.x * 124;
    const int nch = Kdim >> 6;
    const bool isL0 = (layer == 0);
    const u16* Bw = g_Wt[layer];

    float acc[4][6][4];
#pragma unroll
    for (int a = 0; a < 4; a++)
#pragma unroll
        for (int b = 0; b < 6; b++)
#pragma unroll
            for (int c = 0; c < 4; c++) acc[a][b][c] = 0.f;

    auto stage = [&](int c){
        u32 bufb = sb + (c & 1) * CH_BUF;
        int k0 = c << 6;
        bool useLo = isL0 && (c < 2);
        for (int i = t; i < 1024; i += 256){
            int r = i >> 3, cc = i & 7;
            int gr = m0 + r; if (gr > NN-1) gr = NN-1;
            size_t go = (size_t)gr*HROW + k0 + cc*8;
            u32 bo = swz((u32)(r*128 + cc*16));
            cpa16(bufb + CH_A_HI + bo, g_Hh + go);
            if (useLo) cpa16(bufb + CH_A_LO + bo, g_Hl + go);
        }
        const u16* pb = Bw + (size_t)c*12288;
        for (int i = t; i < 1536; i += 256){
            int r = i >> 3, cc = i & 7;
            u32 bo = swz((u32)(r*128 + cc*16));
            cpa16(bufb + CH_B + bo, pb + r*64 + cc*8);
        }
        cpa_commit();
    };

    stage(0);
    for (int c = 0; c < nch; c++){
        if (c+1 < nch) { stage(c+1); cpa_wait<1>(); }
        else cpa_wait<0>();
        __syncthreads();
        u32 bufb = sb + (c & 1) * CH_BUF;
        bool useLo = isL0 && (c < 2);
#pragma unroll
        for (int ks = 0; ks < 4; ks++){
            int arow = wm + (l & 7) + ((l >> 3) & 1) * 8;
            int acol = ks*32 + ((l >> 4) & 1) * 16;
            int brow = wn + (l & 7) + ((l >> 4) & 1) * 8;
            int bcol = ks*32 + ((l >> 3) & 1) * 16;
            // B once per ks, kept live across hi/lo passes
            u32 bw4[3][4];
#pragma unroll
            for (int bi = 0; bi < 3; bi++){
                u32 bo = swz((u32)((brow + bi*16)*128 + bcol));
                ldsm4(bw4[bi][0],bw4[bi][1],bw4[bi][2],bw4[bi][3], bufb + CH_B + bo);
            }
            // hi pass: stream A one mi-tile at a time
#pragma unroll
            for (int mi = 0; mi < 4; mi++){
                u32 aa[4];
                u32 bo = swz((u32)((arow + mi*16)*128 + acol));
                ldsm4(aa[0],aa[1],aa[2],aa[3], bufb + CH_A_HI + bo);
#pragma unroll
                for (int bi = 0; bi < 3; bi++){
                    mma_f16(acc[mi][2*bi],   aa, &bw4[bi][0]);
                    mma_f16(acc[mi][2*bi+1], aa, &bw4[bi][2]);
                }
            }
            // lo pass (layer 0 only), B regs reused
            if (useLo){
#pragma unroll
                for (int mi = 0; mi < 4; mi++){
                    u32 aa[4];
                    u32 bo = swz((u32)((arow + mi*16)*128 + acol));
                    ldsm4(aa[0],aa[1],aa[2],aa[3], bufb + CH_A_LO + bo);
#pragma unroll
                    for (int bi = 0; bi < 3; bi++){
                        mma_f16(acc[mi][2*bi],   aa, &bw4[bi][0]);
                        mma_f16(acc[mi][2*bi+1], aa, &bw4[bi][2]);
                    }
                }
            }
        }
        __syncthreads();
    }

    // ---- combine epilogue: out = P0 + [L|L2]@[P1;P2], via MMA ----
    {
        int i = t;
        int g = i >> 7, kb = (i >> 6) & 1, feat = i & 63;
        u32 bo = CH_BT + g*16384 + kb*8192 + swz((u32)(feat*128 + 124));
        *(u32*)(smem + bo) = 0u;
    }
    for (int i = t; i < 2048; i += 256){
        int blk = i >> 9, rem = i & 511;
        int r = rem >> 3, cc = rem & 7;
        u32 bo = swz((u32)(r*128 + cc*16));
        *(float4*)(smem + CH_AL + blk*8192 + bo) = *(const float4*)(g_LA + blk*4096 + r*64 + cc*8);
    }
    __syncthreads();
    {
        float* stg = (float*)(smem + CH_ST);
#pragma unroll
        for (int mi = 0; mi < 4; mi++)
#pragma unroll
            for (int ni = 0; ni < 6; ni++)
#pragma unroll
                for (int rp = 0; rp < 4; rp += 2){
                    int row = wm + mi*16 + (l>>2) + (rp ? 8 : 0);
                    int col = wn + ni*8 + (l&3)*2;
                    float v0 = acc[mi][ni][rp], v1 = acc[mi][ni][rp+1];
                    if (col < 64){
                        *(float2*)&stg[row*64 + col] = make_float2(v0, v1);
                    } else if (row < 124){
                        int g = (row >= 62) ? 1 : 0;
                        int node = row - g*62;
                        int kbB = (col >= 128) ? 1 : 0;
                        int feat = col - (kbB ? 128 : 64);
                        u32 b0 = CH_BT + g*16384 + kbB*8192 + swz((u32)(feat*128 + node*2));
                        u32 b1 = CH_BT + g*16384 + kbB*8192 + swz((u32)((feat+1)*128 + node*2));
                        *(u16*)(smem + b0) = h16(v0);
                        *(u16*)(smem + b1) = h16(v1);
                    }
                }
    }
    __syncthreads();
    {
        int g = wid >> 2, mt = wid & 3;
        float a2[8][4];
#pragma unroll
        for (int j = 0; j < 8; j++)
#pragma unroll
            for (int r = 0; r < 4; r++) a2[j][r] = 0.f;
#pragma unroll
        for (int kb = 0; kb < 2; kb++)
#pragma unroll
            for (int k16 = 0; k16 < 4; k16++){
                u32 Ah[4], Al4[4];
                u32 boA = swz((u32)((mt*16 + (l&7) + ((l>>3)&1)*8)*128 + k16*32 + ((l>>4)&1)*16));
                ldsm4(Ah[0],Ah[1],Ah[2],Ah[3],     sb + CH_AL + kb*8192 + boA);
                ldsm4(Al4[0],Al4[1],Al4[2],Al4[3], sb + CH_AL + 16384 + kb*8192 + boA);
#pragma unroll
                for (int np = 0; np < 4; np++){
                    u32 Bw4[4];
                    u32 boB = swz((u32)((np*16 + (l&7) + ((l>>4)&1)*8)*128 + k16*32 + ((l>>3)&1)*16));
                    ldsm4(Bw4[0],Bw4[1],Bw4[2],Bw4[3], sb + CH_BT + g*16384 + kb*8192 + boB);
                    mma_f16(a2[2*np],   Ah,  &Bw4[0]);
                    mma_f16(a2[2*np],   Al4, &Bw4[0]);
                    mma_f16(a2[2*np+1], Ah,  &Bw4[2]);
                    mma_f16(a2[2*np+1], Al4, &Bw4[2]);
                }
            }
        float* stg = (float*)(smem + CH_ST);
        size_t hrow0 = ((size_t)(blockIdx.x*2 + g)) * 62;
#pragma unroll
        for (int j = 0; j < 8; j++)
#pragma unroll
            for (int rp = 0; rp < 4; rp += 2){
                int node = mt*16 + (l>>2) + (rp ? 8 : 0);
                if (node >= 62) continue;
                int col = j*8 + (l&3)*2;
                float v0 = a2[j][rp]   + stg[(g*62+node)*64 + col];
                float v1 = a2[j][rp+1] + stg[(g*62+node)*64 + col+1];
                v0 = (col   < 62) ? fmaxf(v0 + bias[col],   0.f) : 0.f;
                v1 = (col+1 < 62) ? fmaxf(v1 + bias[col+1], 0.f) : 0.f;
                size_t off = (hrow0 + node)*HROW + cbase + col;
                *(u32*)(g_Hh + off) = (u32)h16(v0) | ((u32)h16(v1) << 16);
            }
    }
}

// ---------------- mma.sync feats GEMM: A-hi only, N-tile 256, split-K=4 --------
#define FT_A    0
#define FT_B    16384
#define FT_BUF  49152
#define FT_SMEM (3*FT_BUF)   // 147456

__global__ __launch_bounds__(256,1) void mm_feats()
{
    extern __shared__ char smem[];
    const u32 sb = smem_u32(smem);
    const int t = threadIdx.x, wid = t >> 5, l = t & 31;
    const int wm = (wid & 1) * 64, wn = (wid >> 1) * 64;
    const int n0 = blockIdx.x * 256;
    const int m0 = blockIdx.y * 128;
    const int part = blockIdx.z;
    const int cbeg = part * 62;

    float acc[4][8][4];
#pragma unroll
    for (int a = 0; a < 4; a++)
#pragma unroll
        for (int b = 0; b < 8; b++)
#pragma unroll
            for (int c = 0; c < 4; c++) acc[a][b][c] = 0.f;

    auto stage = [&](int cl){
        u32 bufb = sb + (cl % 3) * FT_BUF;
        int c = cbeg + cl;
        int node = c >> 2, col0 = 128 + ((c & 3) << 6);
        for (int i = t; i < 512; i += 256){
            int r = i >> 2, cc = (i & 3) * 2;
            size_t go = ((size_t)(m0 + r)*62 + node)*HROW + col0 + cc*8;
            cpa16(bufb + FT_A + swz((u32)(r*128 + cc*16)), g_Hh + go);
            cpa16(bufb + FT_A + swz((u32)(r*128 + (cc+1)*16)), g_Hh + go + 8);
        }
        const u16* pb = g_Wh1t + ((size_t)c*512 + n0)*64;
        for (int i = t; i < 2048; i += 256){
            int r = i >> 3, cc = i & 7;
            cpa16(bufb + FT_B + swz((u32)(r*128 + cc*16)), pb + r*64 + cc*8);
        }
        cpa_commit();
    };

    stage(0); stage(1);
    for (int cl = 0; cl < 62; cl++){
        if (cl+1 < 62) cpa_wait<1>();
        else cpa_wait<0>();
        __syncthreads();
        if (cl+2 < 62) stage(cl+2);
        u32 bufb = sb + (cl % 3) * FT_BUF;
#pragma unroll
        for (int ks = 0; ks < 4; ks++){
            u32 ah[4][4];
            int arow = wm + (l & 7) + ((l >> 3) & 1) * 8;
            int acol = ks*32 + ((l >> 4) & 1) * 16;
#pragma unroll
            for (int mi = 0; mi < 4; mi++){
                u32 bo = swz((u32)((arow + mi*16)*128 + acol));
                ldsm4(ah[mi][0],ah[mi][1],ah[mi][2],ah[mi][3], bufb + FT_A + bo);
            }
            u32 bw[4][4];
            int brow = wn + (l & 7) + ((l >> 4) & 1) * 8;
            int bcol = ks*32 + ((l >> 3) & 1) * 16;
#pragma unroll
            for (int bi = 0; bi < 4; bi++){
                u32 bo = swz((u32)((brow + bi*16)*128 + bcol));
                ldsm4(bw[bi][0],bw[bi][1],bw[bi][2],bw[bi][3], bufb + FT_B + bo);
            }
#pragma unroll
            for (int mi = 0; mi < 4; mi++)
#pragma unroll
                for (int bi = 0; bi < 4; bi++){
                    mma_f16(acc[mi][2*bi],   ah[mi], &bw[bi][0]);
                    mma_f16(acc[mi][2*bi+1], ah[mi], &bw[bi][2]);
                }
        }
    }

    float* outp = g_G1p + (size_t)part*BATCHG*LINW;
#pragma unroll
    for (int mi = 0; mi < 4; mi++)
#pragma unroll
        for (int ni = 0; ni < 8; ni++){
            int row = m0 + wm + mi*16 + (l >> 2);
            int col = n0 + wn + ni*8 + (l & 3)*2;
            *(float2*)&outp[(size_t)row*LINW + col]     = make_float2(acc[mi][ni][0], acc[mi][ni][1]);
            *(float2*)&outp[(size_t)(row+8)*LINW + col] = make_float2(acc[mi][ni][2], acc[mi][ni][3]);
        }
}

// ---------------- fused split-K reduce + BN1 stats ----------------
__global__ void k_redstats(){
    int c0 = blockIdx.x * 8;
    int t = threadIdx.x;
    int c = c0 + (t & 7);
    float s = 0.f, sq = 0.f;
    for (int r = (t >> 3); r < BATCHG; r += 32){
        size_t off = (size_t)r*LINW + c;
        float v = g_G1p[off]
                + g_G1p[(size_t)BATCHG*LINW + off]
                + g_G1p[(size_t)2*BATCHG*LINW + off]
                + g_G1p[(size_t)3*BATCHG*LINW + off];
        g_G1[off] = v;
        s += v; sq += v*v;
    }
    __shared__ float sh[256], sh2[256];
    sh[t] = s; sh2[t] = sq; __syncthreads();
    for (int o = 128; o >= 8; o >>= 1){
        if (t < o){ sh[t] += sh[t+o]; sh2[t] += sh2[t+o]; }
        __syncthreads();
    }
    if (t < 8){
        float m = sh[t] * (1.f/BATCHG);
        float v = sh2[t] * (1.f/BATCHG) - m*m;
        g_mean[c0+t] = m;
        g_rstd[c0+t] = rsqrtf(v + 1e-5f);
    }
}

// ---------------- SIMT fp32 GEMM for Wh2, BN1+ReLU fused, G2 partial stats ----
__global__ void gemm_s_bn(const float* __restrict__ A, const float* __restrict__ B,
                          float* __restrict__ C,
                          const float* __restrict__ gamma, const float* __restrict__ beta)
{
    __shared__ float As[16][68];
    __shared__ float Bs[16][64];
    __shared__ float Ssum[16][64], Ssq[16][64];
    int t = threadIdx.x;
    int m0 = blockIdx.y * 64, n0 = blockIdx.x * 64;
    int ty = t >> 4, tx = t & 15;
    int am = t >> 2, ak = (t & 3) * 4;
    int bk = t >> 4, bn = (t & 15) * 4;
    float acc[4][4];
#pragma unroll
    for (int i = 0; i < 4; i++)
#pragma unroll
        for (int j = 0; j < 4; j++) acc[i][j] = 0.f;
    for (int k0 = 0; k0 < LINW; k0 += 16) {
        float4 av = *reinterpret_cast<const float4*>(A + (size_t)(m0+am)*LINW + k0 + ak);
        float va[4] = {av.x, av.y, av.z, av.w};
#pragma unroll
        for (int q = 0; q < 4; q++){
            int k = k0 + ak + q;
            va[q] = fmaxf((va[q] - g_mean[k]) * g_rstd[k] * gamma[k] + beta[k], 0.f);
            As[ak+q][am] = va[q];
        }
        float4 bv = *reinterpret_cast<const float4*>(B + (size_t)(k0+bk)*LIN2 + n0 + bn);
        *reinterpret_cast<float4*>(&Bs[bk][bn]) = bv;
        __syncthreads();
#pragma unroll
        for (int k = 0; k < 16; k++) {
            float4 a4 = *reinterpret_cast<const float4*>(&As[k][ty*4]);
            float4 b4 = *reinterpret_cast<const float4*>(&Bs[k][tx*4]);
            float a[4] = {a4.x, a4.y, a4.z, a4.w};
            float b[4] = {b4.x, b4.y, b4.z, b4.w};
#pragma unroll
            for (int i = 0; i < 4; i++)
#pragma unroll
                for (int j = 0; j < 4; j++) acc[i][j] += a[i]*b[j];
        }
        __syncthreads();
    }
#pragma unroll
    for (int i = 0; i < 4; i++) {
        float4 v = make_float4(acc[i][0], acc[i][1], acc[i][2], acc[i][3]);
        *reinterpret_cast<float4*>(C + (size_t)(m0 + ty*4 + i)*LIN2 + n0 + tx*4) = v;
    }
    {
        float s[4], q[4];
#pragma unroll
        for (int j = 0; j < 4; j++){
            s[j] = acc[0][j] + acc[1][j] + acc[2][j] + acc[3][j];
            q[j] = acc[0][j]*acc[0][j] + acc[1][j]*acc[1][j]
                 + acc[2][j]*acc[2][j] + acc[3][j]*acc[3][j];
        }
#pragma unroll
        for (int j = 0; j < 4; j++){ Ssum[ty][tx*4+j] = s[j]; Ssq[ty][tx*4+j] = q[j]; }
        __syncthreads();
        if (t < 64){
            float ss = 0.f, qq = 0.f;
#pragma unroll
            for (int m = 0; m < 16; m++){ ss += Ssum[m][t]; qq += Ssq[m][t]; }
            g_S2p[0][blockIdx.y][n0 + t] = ss;
            g_S2p[1][blockIdx.y][n0 + t] = qq;
        }
    }
}

// ---------------- final: reduce G2 stats in-block, BN2+ReLU+logits+softmax ----
__global__ void k_final_bn(const float* __restrict__ Wh3, const float* __restrict__ bh3,
                           const float* __restrict__ gamma, const float* __restrict__ beta,
                           float* __restrict__ out){
    __shared__ float sm[LIN2], sr[LIN2];
    int t = threadIdx.x;
    {
        int c = t;
        float s = 0.f, q = 0.f;
#pragma unroll 8
        for (int mb = 0; mb < 32; mb++){ s += g_S2p[0][mb][c]; q += g_S2p[1][mb][c]; }
        float m = s * (1.f/BATCHG);
        float v = q * (1.f/BATCHG) - m*m;
        sm[c] = m;
        sr[c] = rsqrtf(v + 1e-5f);
    }
    __syncthreads();
    int r = blockIdx.x*256 + t;
    if (r >= BATCHG) return;
    const float* h = g_G2 + (size_t)r * LIN2;
    float a0 = bh3[0], a1 = bh3[1], a2 = bh3[2];
    for (int k = 0; k < LIN2; k++) {
        float v = fmaxf((h[k] - sm[k]) * sr[k] * gamma[k] + beta[k], 0.f);
        a0 += v * Wh3[k*3+0];
        a1 += v * Wh3[k*3+1];
        a2 += v * Wh3[k*3+2];
    }
    float mx = fmaxf(a0, fmaxf(a1, a2));
    float e0 = expf(a0-mx), e1 = expf(a1-mx), e2 = expf(a2-mx);
    float inv = 1.f / (e0+e1+e2);
    out[r*3+0] = e0*inv; out[r*3+1] = e1*inv; out[r*3+2] = e2*inv;
}

// ---------------- launch ----------------
extern "C" void kernel_launch(void* const* d_in, const int* in_sizes, int n_in,
                              void* d_out, int out_size) {
    const float* x   = (const float*)d_in[0];
    const int*   ei  = (const int*)  d_in[1];
    const float* W1  = (const float*)d_in[2];
    const float* W2  = (const float*)d_in[4];
    const float* W3  = (const float*)d_in[6];
    const float* W4  = (const float*)d_in[8];
    const float* bb[4] = {(const float*)d_in[3], (const float*)d_in[5],
                          (const float*)d_in[7], (const float*)d_in[9]};
    const float* Wh1 = (const float*)d_in[10];
    const float* g1  = (const float*)d_in[12];
    const float* be1 = (const float*)d_in[13];
    const float* Wh2 = (const float*)d_in[14];
    const float* g2  = (const float*)d_in[16];
    const float* be2 = (const float*)d_in[17];
    const float* Wh3 = (const float*)d_in[18];
    const float* bh3 = (const float*)d_in[19];
    float* out = (float*)d_out;

    int E = in_sizes[1] / 2;
    const int* row = ei;
    const int* col = ei + E;

    float *hG1, *hG2;
    cudaGetSymbolAddress((void**)&hG1, g_G1);
    cudaGetSymbolAddress((void**)&hG2, g_G2);

    cudaFuncSetAttribute(mm_cheb,  cudaFuncAttributeMaxDynamicSharedMemorySize, CH_SMEM);
    cudaFuncSetAttribute(mm_feats, cudaFuncAttributeMaxDynamicSharedMemorySize, FT_SMEM);

    const int DPAD[4] = {128, 192, 256, 320};

    // merged prep (graph + weights + Wh1t + init H)
    k_prep_all<<<PB_TOT, 512>>>(x, row, col, W1, W2, W3, W4, Wh1);

    // 4 cheb layers (GEMM + fused MMA combine)
    for (int i = 0; i < 4; i++)
        mm_cheb<<<1024, 256, CH_SMEM>>>(i, DPAD[i], bb[i], 128 + 64*i);

    // MLP head
    mm_feats<<<dim3(2, 16, KSPLIT), 256, FT_SMEM>>>();
    k_redstats<<<64, 256>>>();
    gemm_s_bn<<<dim3(LIN2/64, BATCHG/64), 256>>>(hG1, Wh2, hG2, g1, be1);
    k_final_bn<<<(BATCHG + 255)/256, 256>>>(Wh3, bh3, g2, be2, out);
}